// round 16
// baseline (speedup 1.0000x reference)
#include <cuda_runtime.h>
#include <cuda_bf16.h>
#include <mma.h>
#include <cstdint>

using namespace nvcuda;

#define N_NODES     500000
#define NODE_SIZE   512
#define GLOBAL_SIZE 256
#define HIDDEN_SIZE 1024
#define N_GRAPHS    4096
#define INPUT_SIZE  768

typedef __nv_bfloat16 bf16;

// ---------------- scratch (device globals; no allocation) ----------------
__device__ bf16  g_Ahi[N_GRAPHS * INPUT_SIZE];
__device__ bf16  g_Alo[N_GRAPHS * INPUT_SIZE];
__device__ bf16  g_W1Thi[HIDDEN_SIZE * INPUT_SIZE];   // [N=1024][K=768]
__device__ bf16  g_W1Tlo[HIDDEN_SIZE * INPUT_SIZE];
__device__ bf16  g_W2Thi[GLOBAL_SIZE * HIDDEN_SIZE];  // [N=256][K=1024]
__device__ bf16  g_W2Tlo[GLOBAL_SIZE * HIDDEN_SIZE];
__device__ bf16  g_Hhi[N_GRAPHS * HIDDEN_SIZE];
__device__ bf16  g_Hlo[N_GRAPHS * HIDDEN_SIZE];
__device__ float g_C1[N_GRAPHS * HIDDEN_SIZE];        // gemm1a partials (fp32)
__device__ float g_P[2][N_GRAPHS * GLOBAL_SIZE];      // gemm2 split-K partials
__device__ float g_zero_bias[GLOBAL_SIZE];            // zero-initialized

// ---------------- helpers ----------------
__device__ __forceinline__ uint32_t smem_u32(const void* p) {
    uint32_t a;
    asm("{ .reg .u64 t; cvta.to.shared.u64 t, %1; cvt.u32.u64 %0, t; }" : "=r"(a) : "l"(p));
    return a;
}
__device__ __forceinline__ void cp16(uint32_t dst, const void* src) {
    asm volatile("cp.async.cg.shared.global [%0], [%1], 16;" :: "r"(dst), "l"(src));
}
__device__ __forceinline__ void cp_commit() {
    asm volatile("cp.async.commit_group;" ::: "memory");
}
template <int N>
__device__ __forceinline__ void cp_wait() {
    asm volatile("cp.async.wait_group %0;" :: "n"(N) : "memory");
}
__device__ __forceinline__ void split_bf(float v, bf16& hi, bf16& lo) {
    hi = __float2bfloat16(v);
    lo = __float2bfloat16(v - __bfloat162float(hi));
}
__device__ __forceinline__ float selu_f(float v) {
    const float alpha = 1.6732632423543772f;
    const float scale = 1.0507009873554805f;
    return v > 0.0f ? scale * v : scale * alpha * (expf(v) - 1.0f);
}

// ---------------- kernel: u part -> A cols [0, 256) ----------------
__global__ __launch_bounds__(64) void u_part_kernel(const float* __restrict__ u) {
    const int g = blockIdx.x;
    const int tid = threadIdx.x;   // 64 threads x float4 = 256 cols
    float4 v = *(const float4*)&u[(size_t)g * GLOBAL_SIZE + tid * 4];
    size_t base = (size_t)g * INPUT_SIZE + tid * 4;
    bf16 h, l;
    split_bf(v.x, h, l); g_Ahi[base]     = h; g_Alo[base]     = l;
    split_bf(v.y, h, l); g_Ahi[base + 1] = h; g_Alo[base + 1] = l;
    split_bf(v.z, h, l); g_Ahi[base + 2] = h; g_Alo[base + 2] = l;
    split_bf(v.w, h, l); g_Ahi[base + 3] = h; g_Alo[base + 3] = l;
}

// ---------------- kernel: per-graph mean -> A cols [256, 768) ----------
__global__ __launch_bounds__(128) void mean_concat_kernel(
    const float* __restrict__ x, const int* __restrict__ batch)
{
    const int g = blockIdx.x;
    const int tid = threadIdx.x;

    int lo = 0, hi = N_NODES;
    while (lo < hi) { int mid = (lo + hi) >> 1; if (__ldg(&batch[mid]) < g) lo = mid + 1; else hi = mid; }
    const int start = lo;
    hi = N_NODES;
    while (lo < hi) { int mid = (lo + hi) >> 1; if (__ldg(&batch[mid]) < g + 1) lo = mid + 1; else hi = mid; }
    const int end = lo;

    float4 acc = make_float4(0.f, 0.f, 0.f, 0.f);
    const float* xp = x + (size_t)start * NODE_SIZE + tid * 4;
#pragma unroll 4
    for (int r = start; r < end; ++r) {
        float4 v = *(const float4*)xp;
        acc.x += v.x; acc.y += v.y; acc.z += v.z; acc.w += v.w;
        xp += NODE_SIZE;
    }
    const int cnt = end - start;
    const float inv = (cnt > 0) ? 1.0f / (float)cnt : 0.0f;
    acc.x *= inv; acc.y *= inv; acc.z *= inv; acc.w *= inv;

    size_t base = (size_t)g * INPUT_SIZE + GLOBAL_SIZE + tid * 4;
    bf16 h, l;
    split_bf(acc.x, h, l); g_Ahi[base]     = h; g_Alo[base]     = l;
    split_bf(acc.y, h, l); g_Ahi[base + 1] = h; g_Alo[base + 1] = l;
    split_bf(acc.z, h, l); g_Ahi[base + 2] = h; g_Alo[base + 2] = l;
    split_bf(acc.w, h, l); g_Ahi[base + 3] = h; g_Alo[base + 3] = l;
}

// ---------------- prep: coalesced 32x32 tiled transpose + split -------------
__global__ __launch_bounds__(256) void prep_w1_kernel(const float* __restrict__ W1) {
    __shared__ float tile[32][33];
    const int tx = threadIdx.x & 31;
    const int ty = threadIdx.x >> 5;
    const int k0 = blockIdx.y * 32;
    const int n0 = blockIdx.x * 32;
#pragma unroll
    for (int q = 0; q < 4; ++q)
        tile[ty + q * 8][tx] = __ldg(&W1[(size_t)(k0 + ty + q * 8) * HIDDEN_SIZE + n0 + tx]);
    __syncthreads();
#pragma unroll
    for (int q = 0; q < 4; ++q) {
        int n = n0 + ty + q * 8;
        float v = tile[tx][ty + q * 8];
        bf16 hi, lo; split_bf(v, hi, lo);
        g_W1Thi[(size_t)n * INPUT_SIZE + k0 + tx] = hi;
        g_W1Tlo[(size_t)n * INPUT_SIZE + k0 + tx] = lo;
    }
}
__global__ __launch_bounds__(256) void prep_w2_kernel(const float* __restrict__ W2) {
    __shared__ float tile[32][33];
    const int tx = threadIdx.x & 31;
    const int ty = threadIdx.x >> 5;
    const int k0 = blockIdx.y * 32;
    const int n0 = blockIdx.x * 32;
#pragma unroll
    for (int q = 0; q < 4; ++q)
        tile[ty + q * 8][tx] = __ldg(&W2[(size_t)(k0 + ty + q * 8) * GLOBAL_SIZE + n0 + tx]);
    __syncthreads();
#pragma unroll
    for (int q = 0; q < 4; ++q) {
        int n = n0 + ty + q * 8;
        float v = tile[tx][ty + q * 8];
        bf16 hi, lo; split_bf(v, hi, lo);
        g_W2Thi[(size_t)n * HIDDEN_SIZE + k0 + tx] = hi;
        g_W2Tlo[(size_t)n * HIDDEN_SIZE + k0 + tx] = lo;
    }
}

// ---------------- cp.async double-buffered wmma bf16-split GEMM --------------
// C = A @ B^T, fp32 accum; 3 passes AhBh + AhBl + AlBh. BN=128, BK=32, PAD=40.
// MODE 0: epilogue = bias -> fp32 Cf.   MODE 1: epilogue = +partial Pf, SELU,
// split -> g_Hhi/g_Hlo.
template <int BM, int MODE>
__device__ __forceinline__ void gemm_pipe_body(
    const bf16* __restrict__ Ah, const bf16* __restrict__ Al,
    const bf16* __restrict__ Bh, const bf16* __restrict__ Bl,
    const float* __restrict__ bias, const float* __restrict__ Pf,
    float* __restrict__ Cf,
    int K_STRIDE, int K_LEN, int N_TOTAL)
{
    constexpr int BN = 128, BK = 32, PAD = 40;
    constexpr int WM = BM / 2;
    constexpr int MF = WM / 16;
    constexpr int NF = 2;
    constexpr int ATILE = BM * PAD;
    constexpr int BTILE = BN * PAD;
    constexpr int STAGE = 2 * ATILE + 2 * BTILE;
    constexpr int CLD = 132;

    extern __shared__ __align__(16) char sm_raw[];
    bf16* sm = (bf16*)sm_raw;
    const uint32_t sm_base = smem_u32(sm);

    const int tid = threadIdx.x;
    const int wid = tid >> 5;
    const int warp_m = wid >> 2;
    const int warp_n = wid & 3;
    const int m0 = blockIdx.y * BM;
    const int n0 = blockIdx.x * BN;

    wmma::fragment<wmma::accumulator, 16, 16, 16, float> acc[MF][NF];
#pragma unroll
    for (int mi = 0; mi < MF; ++mi)
#pragma unroll
        for (int ni = 0; ni < NF; ++ni) wmma::fill_fragment(acc[mi][ni], 0.0f);

    auto load_stage = [&](int s, int t) {
        const int k0 = t * BK;
        const uint32_t sb = sm_base + (uint32_t)s * STAGE * 2;
#pragma unroll
        for (int q = 0; q < BM * 4 / 256; ++q) {
            int idx = tid + q * 256;
            int r = idx >> 2, c8 = (idx & 3) * 8;
            uint32_t d = sb + (uint32_t)(r * PAD + c8) * 2;
            cp16(d,                       &Ah[(size_t)(m0 + r) * K_STRIDE + k0 + c8]);
            cp16(d + (uint32_t)ATILE * 2, &Al[(size_t)(m0 + r) * K_STRIDE + k0 + c8]);
        }
#pragma unroll
        for (int q = 0; q < BN * 4 / 256; ++q) {
            int idx = tid + q * 256;
            int r = idx >> 2, c8 = (idx & 3) * 8;
            uint32_t d = sb + (uint32_t)(2 * ATILE + r * PAD + c8) * 2;
            cp16(d,                       &Bh[(size_t)(n0 + r) * K_STRIDE + k0 + c8]);
            cp16(d + (uint32_t)BTILE * 2, &Bl[(size_t)(n0 + r) * K_STRIDE + k0 + c8]);
        }
        cp_commit();
    };

    auto compute_stage = [&](int s) {
        bf16* sAh = sm + (size_t)s * STAGE;
        bf16* sAl = sAh + ATILE;
        bf16* sBh = sAl + ATILE;
        bf16* sBl = sBh + BTILE;
#pragma unroll
        for (int ks = 0; ks < BK / 16; ++ks) {
            wmma::fragment<wmma::matrix_b, 16, 16, 16, bf16, wmma::col_major> fbh[NF], fbl[NF];
#pragma unroll
            for (int ni = 0; ni < NF; ++ni) {
                wmma::load_matrix_sync(fbh[ni], &sBh[(warp_n * 32 + ni * 16) * PAD + ks * 16], PAD);
                wmma::load_matrix_sync(fbl[ni], &sBl[(warp_n * 32 + ni * 16) * PAD + ks * 16], PAD);
            }
#pragma unroll
            for (int mi = 0; mi < MF; ++mi) {
                wmma::fragment<wmma::matrix_a, 16, 16, 16, bf16, wmma::row_major> fah, fal;
                wmma::load_matrix_sync(fah, &sAh[(warp_m * WM + mi * 16) * PAD + ks * 16], PAD);
                wmma::load_matrix_sync(fal, &sAl[(warp_m * WM + mi * 16) * PAD + ks * 16], PAD);
#pragma unroll
                for (int ni = 0; ni < NF; ++ni) {
                    wmma::mma_sync(acc[mi][ni], fah, fbh[ni], acc[mi][ni]);
                    wmma::mma_sync(acc[mi][ni], fah, fbl[ni], acc[mi][ni]);
                    wmma::mma_sync(acc[mi][ni], fal, fbh[ni], acc[mi][ni]);
                }
            }
        }
    };

    const int nk = K_LEN / BK;
    load_stage(0, 0);
    for (int t = 0; t < nk; ++t) {
        if (t + 1 < nk) {
            load_stage((t + 1) & 1, t + 1);
            cp_wait<1>();
        } else {
            cp_wait<0>();
        }
        __syncthreads();
        compute_stage(t & 1);
        __syncthreads();
    }

    // ---- fused epilogue via smem staging ----
    float* sC = (float*)sm;
#pragma unroll
    for (int mi = 0; mi < MF; ++mi)
#pragma unroll
        for (int ni = 0; ni < NF; ++ni)
            wmma::store_matrix_sync(
                &sC[(warp_m * WM + mi * 16) * CLD + warp_n * 32 + ni * 16],
                acc[mi][ni], CLD, wmma::mem_row_major);
    __syncthreads();

    for (int idx = tid; idx < BM * (BN / 4); idx += 256) {
        int r = idx / (BN / 4);
        int c = (idx % (BN / 4)) * 4;
        float v0 = sC[r * CLD + c];
        float v1 = sC[r * CLD + c + 1];
        float v2 = sC[r * CLD + c + 2];
        float v3 = sC[r * CLD + c + 3];
        if (MODE == 0) {
            float4 bv = *(const float4*)&bias[n0 + c];
            float4 o4;
            o4.x = v0 + bv.x; o4.y = v1 + bv.y; o4.z = v2 + bv.z; o4.w = v3 + bv.w;
            *(float4*)&Cf[(size_t)(m0 + r) * N_TOTAL + n0 + c] = o4;
        } else {
            float4 pv = *(const float4*)&Pf[(size_t)(m0 + r) * N_TOTAL + n0 + c];
            v0 = selu_f(v0 + pv.x); v1 = selu_f(v1 + pv.y);
            v2 = selu_f(v2 + pv.z); v3 = selu_f(v3 + pv.w);
            bf16 h0, l0, h1, l1, h2, l2, h3, l3;
            split_bf(v0, h0, l0); split_bf(v1, h1, l1);
            split_bf(v2, h2, l2); split_bf(v3, h3, l3);
            size_t o = (size_t)(m0 + r) * N_TOTAL + n0 + c;
            *(__nv_bfloat162*)&g_Hhi[o]     = __nv_bfloat162(h0, h1);
            *(__nv_bfloat162*)&g_Hhi[o + 2] = __nv_bfloat162(h2, h3);
            *(__nv_bfloat162*)&g_Hlo[o]     = __nv_bfloat162(l0, l1);
            *(__nv_bfloat162*)&g_Hlo[o + 2] = __nv_bfloat162(l2, l3);
        }
    }
}

// Wrappers: device-global scratch referenced FROM DEVICE CODE only.
// gemm1a: K [0,256) (u columns) + b1 -> fp32 partials g_C1. Runs concurrent
// with the mean kernel (fork stream).
__global__ __launch_bounds__(256, 2) void gemm1a_kernel(const float* __restrict__ b1) {
    gemm_pipe_body<128, 0>(g_Ahi, g_Alo, g_W1Thi, g_W1Tlo, b1, nullptr, g_C1,
                           INPUT_SIZE, GLOBAL_SIZE, HIDDEN_SIZE);
}
// gemm1b: K [256,768) (mean columns) + partial -> selu -> split H.
__global__ __launch_bounds__(256, 2) void gemm1b_kernel() {
    gemm_pipe_body<128, 1>(g_Ahi + GLOBAL_SIZE, g_Alo + GLOBAL_SIZE,
                           g_W1Thi + GLOBAL_SIZE, g_W1Tlo + GLOBAL_SIZE,
                           nullptr, g_C1, nullptr,
                           INPUT_SIZE, NODE_SIZE, HIDDEN_SIZE);
}
// gemm2: split-K halves -> g_P[z] (zero bias).
__global__ __launch_bounds__(256, 2) void gemm2_kernel() {
    const int z = blockIdx.z;
    const int koff = z * (HIDDEN_SIZE / 2);
    gemm_pipe_body<64, 0>(g_Hhi + koff, g_Hlo + koff,
                          g_W2Thi + koff, g_W2Tlo + koff,
                          g_zero_bias, nullptr, g_P[z],
                          HIDDEN_SIZE, HIDDEN_SIZE / 2, GLOBAL_SIZE);
}
// reduce: out = P0 + P1 + b2
__global__ __launch_bounds__(256) void reduce_kernel(float* __restrict__ out,
                                                     const float* __restrict__ b2) {
    int i4 = (blockIdx.x * 256 + threadIdx.x) * 4;
    if (i4 >= N_GRAPHS * GLOBAL_SIZE) return;
    float4 p0 = *(const float4*)&g_P[0][i4];
    float4 p1 = *(const float4*)&g_P[1][i4];
    float4 bv = *(const float4*)&b2[i4 & (GLOBAL_SIZE - 1)];
    float4 o;
    o.x = p0.x + p1.x + bv.x;
    o.y = p0.y + p1.y + bv.y;
    o.z = p0.z + p1.z + bv.z;
    o.w = p0.w + p1.w + bv.w;
    *(float4*)&out[i4] = o;
}

// ---------------- launch ----------------
extern "C" void kernel_launch(void* const* d_in, const int* in_sizes, int n_in,
                              void* d_out, int out_size)
{
    const float* x     = nullptr;   // 256,000,000
    const float* u     = nullptr;   //   1,048,576
    const int*   batch = nullptr;   //     500,000 (int32 on device)
    const float* W1    = nullptr;   //     786,432
    const float* b1    = nullptr;   //       1,024
    const float* W2    = nullptr;   //     262,144
    const float* b2    = nullptr;   //         256

    for (int i = 0; i < n_in; ++i) {
        switch (in_sizes[i]) {
            case 256000000: x     = (const float*)d_in[i]; break;
            case 1048576:   u     = (const float*)d_in[i]; break;
            case 500000:    batch = (const int*)d_in[i];   break;
            case 786432:    W1    = (const float*)d_in[i]; break;
            case 1024:      b1    = (const float*)d_in[i]; break;
            case 262144:    W2    = (const float*)d_in[i]; break;
            case 256:       b2    = (const float*)d_in[i]; break;
            default: break; // edge_index (2000), edge_attr (16000): unused
        }
    }
    float* out = (float*)d_out;
    if (!x || !u || !batch || !W1 || !b1 || !W2 || !b2) return;

    // persistent side stream + events (created once, OUTSIDE capture: the
    // harness's first call is the un-captured correctness run)
    static cudaStream_t s2 = nullptr;
    static cudaEvent_t ev_fork = nullptr, ev_join = nullptr;
    if (!s2) {
        cudaStreamCreateWithFlags(&s2, cudaStreamNonBlocking);
        cudaEventCreateWithFlags(&ev_fork, cudaEventDisableTiming);
        cudaEventCreateWithFlags(&ev_join, cudaEventDisableTiming);
    }

    constexpr int PAD = 40, CLD = 132;
    const int stage1 = (2 * 128 * PAD + 2 * 128 * PAD) * 2;
    const int smem1  = (2 * stage1 > 128 * CLD * 4) ? 2 * stage1 : 128 * CLD * 4;
    const int stage2 = (2 * 64 * PAD + 2 * 128 * PAD) * 2;
    const int smem2  = (2 * stage2 > 64 * CLD * 4) ? 2 * stage2 : 64 * CLD * 4;
    cudaFuncSetAttribute(gemm1a_kernel,
                         cudaFuncAttributeMaxDynamicSharedMemorySize, smem1);
    cudaFuncSetAttribute(gemm1b_kernel,
                         cudaFuncAttributeMaxDynamicSharedMemorySize, smem1);
    cudaFuncSetAttribute(gemm2_kernel,
                         cudaFuncAttributeMaxDynamicSharedMemorySize, smem2);

    // ---- fork: side stream does u-part + preps + gemm1a (independent of x) ----
    cudaEventRecord(ev_fork, 0);
    cudaStreamWaitEvent(s2, ev_fork, 0);

    u_part_kernel<<<N_GRAPHS, 64, 0, s2>>>(u);
    {
        dim3 g1(HIDDEN_SIZE / 32, INPUT_SIZE / 32);
        prep_w1_kernel<<<g1, 256, 0, s2>>>(W1);
        dim3 g2(GLOBAL_SIZE / 32, HIDDEN_SIZE / 32);
        prep_w2_kernel<<<g2, 256, 0, s2>>>(W2);
    }
    {
        dim3 grid(HIDDEN_SIZE / 128, N_GRAPHS / 128);
        gemm1a_kernel<<<grid, 256, smem1, s2>>>(b1);
    }
    cudaEventRecord(ev_join, s2);

    // ---- main stream: mean (the long pole), then join ----
    mean_concat_kernel<<<N_GRAPHS, 128>>>(x, batch);
    cudaStreamWaitEvent(0, ev_join, 0);

    // gemm1b: mean columns + partial -> H
    {
        dim3 grid(HIDDEN_SIZE / 128, N_GRAPHS / 128);
        gemm1b_kernel<<<grid, 256, smem1>>>();
    }
    // gemm2 split-K partials
    {
        dim3 grid(GLOBAL_SIZE / 128, N_GRAPHS / 64, 2);
        gemm2_kernel<<<grid, 256, smem2>>>();
    }
    // out = P0 + P1 + b2
    {
        int n4 = N_GRAPHS * GLOBAL_SIZE / 4;
        reduce_kernel<<<(n4 + 255) / 256, 256>>>(out, b2);
    }
}

// round 17
// speedup vs baseline: 1.0210x; 1.0210x over previous
#include <cuda_runtime.h>
#include <cuda_bf16.h>
#include <mma.h>
#include <cstdint>

using namespace nvcuda;

#define N_NODES     500000
#define NODE_SIZE   512
#define GLOBAL_SIZE 256
#define HIDDEN_SIZE 1024
#define N_GRAPHS    4096
#define INPUT_SIZE  768
#define SPLITK      4

typedef __nv_bfloat16 bf16;

// ---------------- scratch (device globals; no allocation) ----------------
__device__ bf16  g_Ahi[N_GRAPHS * INPUT_SIZE];
__device__ bf16  g_Alo[N_GRAPHS * INPUT_SIZE];
__device__ bf16  g_W1Thi[HIDDEN_SIZE * INPUT_SIZE];   // [N=1024][K=768]
__device__ bf16  g_W1Tlo[HIDDEN_SIZE * INPUT_SIZE];
__device__ bf16  g_W2Thi[GLOBAL_SIZE * HIDDEN_SIZE];  // [N=256][K=1024]
__device__ bf16  g_W2Tlo[GLOBAL_SIZE * HIDDEN_SIZE];
__device__ bf16  g_Hhi[N_GRAPHS * HIDDEN_SIZE];
__device__ bf16  g_Hlo[N_GRAPHS * HIDDEN_SIZE];
__device__ float g_P[SPLITK][N_GRAPHS * GLOBAL_SIZE]; // split-K partials
__device__ float g_zero_bias[GLOBAL_SIZE];            // zero-initialized

// ---------------- helpers ----------------
__device__ __forceinline__ uint32_t smem_u32(const void* p) {
    uint32_t a;
    asm("{ .reg .u64 t; cvta.to.shared.u64 t, %1; cvt.u32.u64 %0, t; }" : "=r"(a) : "l"(p));
    return a;
}
__device__ __forceinline__ void cp16(uint32_t dst, const void* src) {
    asm volatile("cp.async.cg.shared.global [%0], [%1], 16;" :: "r"(dst), "l"(src));
}
__device__ __forceinline__ void cp_commit() {
    asm volatile("cp.async.commit_group;" ::: "memory");
}
template <int N>
__device__ __forceinline__ void cp_wait() {
    asm volatile("cp.async.wait_group %0;" :: "n"(N) : "memory");
}
__device__ __forceinline__ void split_bf(float v, bf16& hi, bf16& lo) {
    hi = __float2bfloat16(v);
    lo = __float2bfloat16(v - __bfloat162float(hi));
}
__device__ __forceinline__ float selu_f(float v) {
    const float alpha = 1.6732632423543772f;
    const float scale = 1.0507009873554805f;
    return v > 0.0f ? scale * v : scale * alpha * (expf(v) - 1.0f);
}

// ---------------- kernel 1: fused per-graph mean + concat (R10 version) ----
__global__ __launch_bounds__(128) void mean_concat_kernel(
    const float* __restrict__ x, const int* __restrict__ batch,
    const float* __restrict__ u)
{
    const int g = blockIdx.x;
    const int tid = threadIdx.x;

    int lo = 0, hi = N_NODES;
    while (lo < hi) { int mid = (lo + hi) >> 1; if (__ldg(&batch[mid]) < g) lo = mid + 1; else hi = mid; }
    const int start = lo;
    hi = N_NODES;
    while (lo < hi) { int mid = (lo + hi) >> 1; if (__ldg(&batch[mid]) < g + 1) lo = mid + 1; else hi = mid; }
    const int end = lo;

    float4 acc = make_float4(0.f, 0.f, 0.f, 0.f);
    const float* xp = x + (size_t)start * NODE_SIZE + tid * 4;
#pragma unroll 4
    for (int r = start; r < end; ++r) {
        float4 v = *(const float4*)xp;
        acc.x += v.x; acc.y += v.y; acc.z += v.z; acc.w += v.w;
        xp += NODE_SIZE;
    }
    const int cnt = end - start;
    const float inv = (cnt > 0) ? 1.0f / (float)cnt : 0.0f;
    acc.x *= inv; acc.y *= inv; acc.z *= inv; acc.w *= inv;

    {
        size_t base = (size_t)g * INPUT_SIZE + GLOBAL_SIZE + tid * 4;
        bf16 h, l;
        split_bf(acc.x, h, l); g_Ahi[base]     = h; g_Alo[base]     = l;
        split_bf(acc.y, h, l); g_Ahi[base + 1] = h; g_Alo[base + 1] = l;
        split_bf(acc.z, h, l); g_Ahi[base + 2] = h; g_Alo[base + 2] = l;
        split_bf(acc.w, h, l); g_Ahi[base + 3] = h; g_Alo[base + 3] = l;
    }
    if (tid < GLOBAL_SIZE / 4) {
        float4 v = *(const float4*)&u[(size_t)g * GLOBAL_SIZE + tid * 4];
        size_t base = (size_t)g * INPUT_SIZE + tid * 4;
        bf16 h, l;
        split_bf(v.x, h, l); g_Ahi[base]     = h; g_Alo[base]     = l;
        split_bf(v.y, h, l); g_Ahi[base + 1] = h; g_Alo[base + 1] = l;
        split_bf(v.z, h, l); g_Ahi[base + 2] = h; g_Alo[base + 2] = l;
        split_bf(v.w, h, l); g_Ahi[base + 3] = h; g_Alo[base + 3] = l;
    }
}

// ---------------- prep: coalesced 32x32 tiled transpose + split ----------------
__global__ __launch_bounds__(256) void prep_w1_kernel(const float* __restrict__ W1) {
    __shared__ float tile[32][33];
    const int tx = threadIdx.x & 31;
    const int ty = threadIdx.x >> 5;
    const int k0 = blockIdx.y * 32;
    const int n0 = blockIdx.x * 32;
#pragma unroll
    for (int q = 0; q < 4; ++q)
        tile[ty + q * 8][tx] = __ldg(&W1[(size_t)(k0 + ty + q * 8) * HIDDEN_SIZE + n0 + tx]);
    __syncthreads();
#pragma unroll
    for (int q = 0; q < 4; ++q) {
        int n = n0 + ty + q * 8;
        float v = tile[tx][ty + q * 8];
        bf16 hi, lo; split_bf(v, hi, lo);
        g_W1Thi[(size_t)n * INPUT_SIZE + k0 + tx] = hi;
        g_W1Tlo[(size_t)n * INPUT_SIZE + k0 + tx] = lo;
    }
}
__global__ __launch_bounds__(256) void prep_w2_kernel(const float* __restrict__ W2) {
    __shared__ float tile[32][33];
    const int tx = threadIdx.x & 31;
    const int ty = threadIdx.x >> 5;
    const int k0 = blockIdx.y * 32;
    const int n0 = blockIdx.x * 32;
#pragma unroll
    for (int q = 0; q < 4; ++q)
        tile[ty + q * 8][tx] = __ldg(&W2[(size_t)(k0 + ty + q * 8) * GLOBAL_SIZE + n0 + tx]);
    __syncthreads();
#pragma unroll
    for (int q = 0; q < 4; ++q) {
        int n = n0 + ty + q * 8;
        float v = tile[tx][ty + q * 8];
        bf16 hi, lo; split_bf(v, hi, lo);
        g_W2Thi[(size_t)n * HIDDEN_SIZE + k0 + tx] = hi;
        g_W2Tlo[(size_t)n * HIDDEN_SIZE + k0 + tx] = lo;
    }
}

// ---------------- cp.async double-buffered wmma bf16-split GEMM (R10) ---------
// C = A @ B^T, fp32 accum; 3 passes AhBh + AhBl + AlBh. BN=128, BK=32, PAD=40.
// K_STRIDE = row stride of A/B; K_LEN = summed K extent (split-K support).
template <int BM, bool DO_SELU>
__device__ __forceinline__ void gemm_pipe_body(
    const bf16* __restrict__ Ah, const bf16* __restrict__ Al,
    const bf16* __restrict__ Bh, const bf16* __restrict__ Bl,
    const float* __restrict__ bias,
    bf16* __restrict__ Chi, bf16* __restrict__ Clo, float* __restrict__ Cf,
    int K_STRIDE, int K_LEN, int N_TOTAL)
{
    constexpr int BN = 128, BK = 32, PAD = 40;   // 80B rows (16B-aligned)
    constexpr int WM = BM / 2;
    constexpr int MF = WM / 16;
    constexpr int NF = 2;
    constexpr int ATILE = BM * PAD;
    constexpr int BTILE = BN * PAD;
    constexpr int STAGE = 2 * ATILE + 2 * BTILE;
    constexpr int CLD = 132;

    extern __shared__ __align__(16) char sm_raw[];
    bf16* sm = (bf16*)sm_raw;
    const uint32_t sm_base = smem_u32(sm);

    const int tid = threadIdx.x;
    const int wid = tid >> 5;
    const int warp_m = wid >> 2;
    const int warp_n = wid & 3;
    const int m0 = blockIdx.y * BM;
    const int n0 = blockIdx.x * BN;

    wmma::fragment<wmma::accumulator, 16, 16, 16, float> acc[MF][NF];
#pragma unroll
    for (int mi = 0; mi < MF; ++mi)
#pragma unroll
        for (int ni = 0; ni < NF; ++ni) wmma::fill_fragment(acc[mi][ni], 0.0f);

    auto load_stage = [&](int s, int t) {
        const int k0 = t * BK;
        const uint32_t sb = sm_base + (uint32_t)s * STAGE * 2;
#pragma unroll
        for (int q = 0; q < BM * 4 / 256; ++q) {
            int idx = tid + q * 256;
            int r = idx >> 2, c8 = (idx & 3) * 8;
            uint32_t d = sb + (uint32_t)(r * PAD + c8) * 2;
            cp16(d,                       &Ah[(size_t)(m0 + r) * K_STRIDE + k0 + c8]);
            cp16(d + (uint32_t)ATILE * 2, &Al[(size_t)(m0 + r) * K_STRIDE + k0 + c8]);
        }
#pragma unroll
        for (int q = 0; q < BN * 4 / 256; ++q) {
            int idx = tid + q * 256;
            int r = idx >> 2, c8 = (idx & 3) * 8;
            uint32_t d = sb + (uint32_t)(2 * ATILE + r * PAD + c8) * 2;
            cp16(d,                       &Bh[(size_t)(n0 + r) * K_STRIDE + k0 + c8]);
            cp16(d + (uint32_t)BTILE * 2, &Bl[(size_t)(n0 + r) * K_STRIDE + k0 + c8]);
        }
        cp_commit();
    };

    auto compute_stage = [&](int s) {
        bf16* sAh = sm + (size_t)s * STAGE;
        bf16* sAl = sAh + ATILE;
        bf16* sBh = sAl + ATILE;
        bf16* sBl = sBh + BTILE;
#pragma unroll
        for (int ks = 0; ks < BK / 16; ++ks) {
            wmma::fragment<wmma::matrix_b, 16, 16, 16, bf16, wmma::col_major> fbh[NF], fbl[NF];
#pragma unroll
            for (int ni = 0; ni < NF; ++ni) {
                wmma::load_matrix_sync(fbh[ni], &sBh[(warp_n * 32 + ni * 16) * PAD + ks * 16], PAD);
                wmma::load_matrix_sync(fbl[ni], &sBl[(warp_n * 32 + ni * 16) * PAD + ks * 16], PAD);
            }
#pragma unroll
            for (int mi = 0; mi < MF; ++mi) {
                wmma::fragment<wmma::matrix_a, 16, 16, 16, bf16, wmma::row_major> fah, fal;
                wmma::load_matrix_sync(fah, &sAh[(warp_m * WM + mi * 16) * PAD + ks * 16], PAD);
                wmma::load_matrix_sync(fal, &sAl[(warp_m * WM + mi * 16) * PAD + ks * 16], PAD);
#pragma unroll
                for (int ni = 0; ni < NF; ++ni) {
                    wmma::mma_sync(acc[mi][ni], fah, fbh[ni], acc[mi][ni]);
                    wmma::mma_sync(acc[mi][ni], fah, fbl[ni], acc[mi][ni]);
                    wmma::mma_sync(acc[mi][ni], fal, fbh[ni], acc[mi][ni]);
                }
            }
        }
    };

    const int nk = K_LEN / BK;
    load_stage(0, 0);
    for (int t = 0; t < nk; ++t) {
        if (t + 1 < nk) {
            load_stage((t + 1) & 1, t + 1);
            cp_wait<1>();
        } else {
            cp_wait<0>();
        }
        __syncthreads();
        compute_stage(t & 1);
        __syncthreads();
    }

    // ---- fused epilogue via smem staging ----
    float* sC = (float*)sm;
#pragma unroll
    for (int mi = 0; mi < MF; ++mi)
#pragma unroll
        for (int ni = 0; ni < NF; ++ni)
            wmma::store_matrix_sync(
                &sC[(warp_m * WM + mi * 16) * CLD + warp_n * 32 + ni * 16],
                acc[mi][ni], CLD, wmma::mem_row_major);
    __syncthreads();

    for (int idx = tid; idx < BM * (BN / 4); idx += 256) {
        int r = idx / (BN / 4);
        int c = (idx % (BN / 4)) * 4;
        float4 bv = *(const float4*)&bias[n0 + c];
        float v0 = sC[r * CLD + c]     + bv.x;
        float v1 = sC[r * CLD + c + 1] + bv.y;
        float v2 = sC[r * CLD + c + 2] + bv.z;
        float v3 = sC[r * CLD + c + 3] + bv.w;
        if (DO_SELU) {
            v0 = selu_f(v0); v1 = selu_f(v1); v2 = selu_f(v2); v3 = selu_f(v3);
            bf16 h0, l0, h1, l1, h2, l2, h3, l3;
            split_bf(v0, h0, l0); split_bf(v1, h1, l1);
            split_bf(v2, h2, l2); split_bf(v3, h3, l3);
            size_t o = (size_t)(m0 + r) * N_TOTAL + n0 + c;
            *(__nv_bfloat162*)&Chi[o]     = __nv_bfloat162(h0, h1);
            *(__nv_bfloat162*)&Chi[o + 2] = __nv_bfloat162(h2, h3);
            *(__nv_bfloat162*)&Clo[o]     = __nv_bfloat162(l0, l1);
            *(__nv_bfloat162*)&Clo[o + 2] = __nv_bfloat162(l2, l3);
        } else {
            float4 o4; o4.x = v0; o4.y = v1; o4.z = v2; o4.w = v3;
            *(float4*)&Cf[(size_t)(m0 + r) * N_TOTAL + n0 + c] = o4;
        }
    }
}

// Wrappers: device-global scratch referenced FROM DEVICE CODE only.
__global__ __launch_bounds__(256, 2) void gemm1_kernel(const float* __restrict__ b1) {
    gemm_pipe_body<128, true>(g_Ahi, g_Alo, g_W1Thi, g_W1Tlo, b1,
                              g_Hhi, g_Hlo, nullptr,
                              INPUT_SIZE, INPUT_SIZE, HIDDEN_SIZE);
}
// split-K gemm2: blockIdx.z selects K-quarter; partials to g_P (zero bias).
__global__ __launch_bounds__(256, 2) void gemm2_kernel() {
    const int z = blockIdx.z;
    const int koff = z * (HIDDEN_SIZE / SPLITK);
    gemm_pipe_body<64, false>(g_Hhi + koff, g_Hlo + koff,
                              g_W2Thi + koff, g_W2Tlo + koff,
                              g_zero_bias, nullptr, nullptr, g_P[z],
                              HIDDEN_SIZE, HIDDEN_SIZE / SPLITK, GLOBAL_SIZE);
}
// reduce: out = sum_z P[z] + b2
__global__ __launch_bounds__(256) void reduce_kernel(float* __restrict__ out,
                                                     const float* __restrict__ b2) {
    int i4 = (blockIdx.x * 256 + threadIdx.x) * 4;
    if (i4 >= N_GRAPHS * GLOBAL_SIZE) return;
    float4 bv = *(const float4*)&b2[i4 & (GLOBAL_SIZE - 1)];
    float4 o; o.x = bv.x; o.y = bv.y; o.z = bv.z; o.w = bv.w;
#pragma unroll
    for (int z = 0; z < SPLITK; ++z) {
        float4 p = *(const float4*)&g_P[z][i4];
        o.x += p.x; o.y += p.y; o.z += p.z; o.w += p.w;
    }
    *(float4*)&out[i4] = o;
}

// ---------------- launch ----------------
extern "C" void kernel_launch(void* const* d_in, const int* in_sizes, int n_in,
                              void* d_out, int out_size)
{
    const float* x     = nullptr;   // 256,000,000
    const float* u     = nullptr;   //   1,048,576
    const int*   batch = nullptr;   //     500,000 (int32 on device)
    const float* W1    = nullptr;   //     786,432
    const float* b1    = nullptr;   //       1,024
    const float* W2    = nullptr;   //     262,144
    const float* b2    = nullptr;   //         256

    for (int i = 0; i < n_in; ++i) {
        switch (in_sizes[i]) {
            case 256000000: x     = (const float*)d_in[i]; break;
            case 1048576:   u     = (const float*)d_in[i]; break;
            case 500000:    batch = (const int*)d_in[i];   break;
            case 786432:    W1    = (const float*)d_in[i]; break;
            case 1024:      b1    = (const float*)d_in[i]; break;
            case 262144:    W2    = (const float*)d_in[i]; break;
            case 256:       b2    = (const float*)d_in[i]; break;
            default: break; // edge_index (2000), edge_attr (16000): unused
        }
    }
    float* out = (float*)d_out;
    if (!x || !u || !batch || !W1 || !b1 || !W2 || !b2) return;

    constexpr int PAD = 40, CLD = 132;
    const int stage1 = (2 * 128 * PAD + 2 * 128 * PAD) * 2;
    const int smem1  = (2 * stage1 > 128 * CLD * 4) ? 2 * stage1 : 128 * CLD * 4;
    const int stage2 = (2 * 64 * PAD + 2 * 128 * PAD) * 2;
    const int smem2  = (2 * stage2 > 64 * CLD * 4) ? 2 * stage2 : 64 * CLD * 4;
    cudaFuncSetAttribute(gemm1_kernel,
                         cudaFuncAttributeMaxDynamicSharedMemorySize, smem1);
    cudaFuncSetAttribute(gemm2_kernel,
                         cudaFuncAttributeMaxDynamicSharedMemorySize, smem2);

    // 1. A = [u | segment_mean(x, batch)]  (bf16 hi/lo)
    mean_concat_kernel<<<N_GRAPHS, 128>>>(x, batch, u);

    // 2. weight transpose + split (coalesced 32x32 tiles)
    {
        dim3 g1(HIDDEN_SIZE / 32, INPUT_SIZE / 32);
        prep_w1_kernel<<<g1, 256>>>(W1);
        dim3 g2(GLOBAL_SIZE / 32, HIDDEN_SIZE / 32);
        prep_w2_kernel<<<g2, 256>>>(W2);
    }

    // 3. H = selu(A @ W1 + b1) -> bf16 hi/lo   [4096 x 1024]
    {
        dim3 grid(HIDDEN_SIZE / 128, N_GRAPHS / 128);
        gemm1_kernel<<<grid, 256, smem1>>>(b1);
    }
    // 4. split-K partials: P[z] = H[:, z*256:(z+1)*256] @ W2T[:, same]^T
    {
        dim3 grid(GLOBAL_SIZE / 128, N_GRAPHS / 64, SPLITK);
        gemm2_kernel<<<grid, 256, smem2>>>();
    }
    // 5. out = sum_z P[z] + b2
    {
        int n4 = N_GRAPHS * GLOBAL_SIZE / 4;
        reduce_kernel<<<(n4 + 255) / 256, 256>>>(out, b2);
    }
}